// round 8
// baseline (speedup 1.0000x reference)
#include <cuda_runtime.h>
#include <math.h>

// Problem constants (B=4, S=4096, D=2048, E=8, K=2)
#define NTOK    16384
#define DIM     2048
#define NEXP    8
#define NASSIGN (NTOK*2)       // 32768
#define CAP     5120           // int(NTOK*2/8 * 1.25)
#define TOKPW   2              // tokens per warp
#define TOKPB   (8*TOKPW)      // 16 tokens per block
#define NBLK    (NTOK/TOKPB)   // 1024
#define W_BYTES (NEXP*DIM*4)   // 64 KB

// Output layout (float32): [0,32768) indices | [32768,65536) weights |
// [65536] loss | [65537,98305) mask

// Scratch: __device__ globals (zero-init at load; last block resets so every
// graph replay sees zeros).
__device__ int      g_cnt[NEXP];
__device__ float    g_probsum[NEXP];
__device__ unsigned g_done;
__device__ unsigned long long g_bucket[NEXP][NASSIGN];

// Packed fp32x2 FMA (Blackwell): d = a*b + d on two f32 lanes (dim pairs).
__device__ __forceinline__ void ffma2(unsigned long long& d,
                                      unsigned long long a,
                                      unsigned long long b) {
    asm("fma.rn.f32x2 %0, %1, %2, %0;" : "+l"(d) : "l"(a), "l"(b));
}
__device__ __forceinline__ float unpack_sum(unsigned long long v) {
    unsigned lo, hi;
    asm("mov.b64 {%0, %1}, %2;" : "=r"(lo), "=r"(hi) : "l"(v));
    return __uint_as_float(lo) + __uint_as_float(hi);
}

// One fused kernel: GEMV + softmax + top-2 + renorm + stats; LAST arriving
// block computes loss + (rare) capacity drop + resets scratch.
// 2 tokens/warp -> acc=32 regs -> ~80 live regs -> 3 blocks/SM (24 warps).
__global__ __launch_bounds__(256, 3)
void router_main(const float* __restrict__ x,
                 const float* __restrict__ wg,
                 float* __restrict__ out) {
    extern __shared__ float sw[];              // 8*2048 f32 = 64 KB
    __shared__ float s_prob[NEXP];
    __shared__ int   s_cnt[NEXP];
    __shared__ int   s_base[NEXP];
    __shared__ int   s_last;

    const int tid  = threadIdx.x;
    const int warp = tid >> 5;
    const int lane = tid & 31;
    if (tid < NEXP) { s_prob[tid] = 0.0f; s_cnt[tid] = 0; }

    // stage w_gate into shared (one-time; L2-resident after first wave)
    {
        float4* sw4 = (float4*)sw;
        const float4* wg4 = (const float4*)wg;
        #pragma unroll
        for (int i = tid; i < NEXP * DIM / 4; i += 256) sw4[i] = wg4[i];
    }
    __syncthreads();

    const int tbase = (blockIdx.x * 8 + warp) * TOKPW;

    const ulonglong2* xr0 = (const ulonglong2*)(x + (size_t)(tbase + 0) * DIM);
    const ulonglong2* xr1 = (const ulonglong2*)(x + (size_t)(tbase + 1) * DIM);
    const ulonglong2* sw2 = (const ulonglong2*)sw;

    unsigned long long acc[TOKPW][NEXP];
    #pragma unroll
    for (int t = 0; t < TOKPW; t++)
        #pragma unroll
        for (int e = 0; e < NEXP; e++) acc[t][e] = 0ull;

    // Proven loop shape: unroll 2, plain vector loads, dim-pair FFMA2.
    #pragma unroll 2
    for (int i = 0; i < 16; i++) {
        int c = i * 32 + lane;
        ulonglong2 x0 = xr0[c];
        ulonglong2 x1 = xr1[c];
        #pragma unroll
        for (int e = 0; e < NEXP; e++) {
            ulonglong2 wv = sw2[e * (DIM / 4) + c];
            ffma2(acc[0][e], x0.x, wv.x); ffma2(acc[0][e], x0.y, wv.y);
            ffma2(acc[1][e], x1.x, wv.x); ffma2(acc[1][e], x1.y, wv.y);
        }
    }

    // Collapse f32x2 halves, butterfly so lanes 0..TOKPW-1 hold full logits.
    float logit[TOKPW][NEXP];
    #pragma unroll
    for (int t = 0; t < TOKPW; t++)
        #pragma unroll
        for (int e = 0; e < NEXP; e++) {
            float v = unpack_sum(acc[t][e]);
            v += __shfl_xor_sync(0xffffffffu, v, 16);
            v += __shfl_xor_sync(0xffffffffu, v, 8);
            v += __shfl_xor_sync(0xffffffffu, v, 4);
            v += __shfl_xor_sync(0xffffffffu, v, 2);
            v += __shfl_xor_sync(0xffffffffu, v, 1);
            logit[t][e] = v;
        }

    // Per-token epilogue on lanes 0..TOKPW-1; bucket slots block-aggregated.
    int i1 = 0, i2 = 0, r1 = 0, r2 = 0, n0 = 0;
    unsigned long long key1 = 0, key2 = 0;
    bool active = (lane < TOKPW);
    if (active) {
        int token = tbase + lane;
        float p[NEXP];
        float m = logit[lane][0];
        #pragma unroll
        for (int e = 1; e < NEXP; e++) m = fmaxf(m, logit[lane][e]);
        float s = 0.0f;
        #pragma unroll
        for (int e = 0; e < NEXP; e++) { p[e] = expf(logit[lane][e] - m); s += p[e]; }
        float inv = 1.0f / s;
        #pragma unroll
        for (int e = 0; e < NEXP; e++) p[e] *= inv;

        // top-2, ties -> lowest index
        float b1 = p[0];
        #pragma unroll
        for (int e = 1; e < NEXP; e++) if (p[e] > b1) { b1 = p[e]; i1 = e; }
        i2 = -1; float b2 = -1.0f;
        #pragma unroll
        for (int e = 0; e < NEXP; e++) if (e != i1 && p[e] > b2) { b2 = p[e]; i2 = e; }

        float ssum = b1 + b2;
        float w1 = b1 / ssum, w2 = b2 / ssum;

        n0 = token * 2;
        out[n0]     = (float)i1;
        out[n0 + 1] = (float)i2;
        out[NASSIGN + n0]     = w1;
        out[NASSIGN + n0 + 1] = w2;
        out[2 * NASSIGN + 1 + n0]     = 1.0f;
        out[2 * NASSIGN + 1 + n0 + 1] = 1.0f;

        // order-independent keys: (weight desc via bits, flat idx asc via ~n)
        key1 = ((unsigned long long)__float_as_uint(w1) << 32) |
               (unsigned)(~(unsigned)n0);
        key2 = ((unsigned long long)__float_as_uint(w2) << 32) |
               (unsigned)(~(unsigned)(n0 + 1));
        r1 = atomicAdd(&s_cnt[i1], 1);
        r2 = atomicAdd(&s_cnt[i2], 1);

        #pragma unroll
        for (int e = 0; e < NEXP; e++) atomicAdd(&s_prob[e], p[e]);
    }
    __syncthreads();

    // one global atomic per expert per block
    if (tid < NEXP) {
        s_base[tid] = s_cnt[tid] ? atomicAdd(&g_cnt[tid], s_cnt[tid]) : 0;
        atomicAdd(&g_probsum[tid], s_prob[tid]);
    }
    __syncthreads();

    if (active) {
        g_bucket[i1][s_base[i1] + r1] = key1;
        g_bucket[i2][s_base[i2] + r2] = key2;
    }
    __syncthreads();

    // ---- arrival counter: last block finalizes ----
    if (tid == 0) {
        __threadfence();
        unsigned old = atomicAdd(&g_done, 1u);
        s_last = (old == (unsigned)(gridDim.x - 1)) ? 1 : 0;
    }
    __syncthreads();
    if (!s_last) return;

    __shared__ int cnt[NEXP];
    if (tid < NEXP) cnt[tid] = __ldcg(&g_cnt[tid]);
    __syncthreads();

    if (tid == 0) {
        float imp[NEXP], imps = 0.0f;
        #pragma unroll
        for (int e = 0; e < NEXP; e++) { imp[e] = __ldcg(&g_probsum[e]); imps += imp[e]; }
        float loss = 0.0f;
        #pragma unroll
        for (int e = 0; e < NEXP; e++)
            loss += (imp[e] / imps) * ((float)cnt[e] / (float)NASSIGN);
        out[2 * NASSIGN] = (float)NEXP * loss;
    }

    // Capacity drop (rank = #{j: key > key_i}; keep iff rank < CAP). Matches
    // lexsort((-w, expert)) with flat-index tiebreak; rarely triggers
    // (expected per-expert count ~4096 << 5120).
    for (int e = 0; e < NEXP; e++) {
        int c = cnt[e];
        if (c <= CAP) continue;
        for (int i = tid; i < c; i += blockDim.x) {
            unsigned long long ki = __ldcg(&g_bucket[e][i]);
            int rank = 0;
            for (int j = 0; j < c; j++)
                rank += (__ldcg(&g_bucket[e][j]) > ki) ? 1 : 0;
            if (rank >= CAP) {
                unsigned n = ~(unsigned)(ki & 0xffffffffull);
                out[2 * NASSIGN + 1 + n] = 0.0f;
            }
        }
    }
    __syncthreads();

    if (tid < NEXP) { g_cnt[tid] = 0; g_probsum[tid] = 0.0f; }
    if (tid == 0)   { g_done = 0u; __threadfence(); }
}

extern "C" void kernel_launch(void* const* d_in, const int* in_sizes, int n_in,
                              void* d_out, int out_size) {
    const float* x  = (const float*)d_in[0];
    const float* wg = (const float*)d_in[1];
    float* out = (float*)d_out;
    (void)in_sizes; (void)n_in; (void)out_size;

    cudaFuncSetAttribute(router_main, cudaFuncAttributeMaxDynamicSharedMemorySize,
                         W_BYTES);

    router_main<<<NBLK, 256, W_BYTES>>>(x, wg, out);
}

// round 9
// speedup vs baseline: 1.1291x; 1.1291x over previous
#include <cuda_runtime.h>
#include <math.h>

// Problem constants (B=4, S=4096, D=2048, E=8, K=2)
#define NTOK    16384
#define DIM     2048
#define NEXP    8
#define NASSIGN (NTOK*2)       // 32768
#define CAP     5120           // int(NTOK*2/8 * 1.25)
#define TOKPW   3              // tokens per warp
#define TOKPB   (8*TOKPW)      // 24 tokens per block
#define NBLK    ((NTOK + TOKPB - 1) / TOKPB)   // 683 (last block partial)
#define W_BYTES (NEXP*DIM*4)   // 64 KB

// Output layout (float32): [0,32768) indices | [32768,65536) weights |
// [65536] loss | [65537,98305) mask

// Scratch: __device__ globals (zero-init at load; last block resets so every
// graph replay sees zeros).
__device__ int      g_cnt[NEXP];
__device__ float    g_probsum[NEXP];
__device__ unsigned g_done;
__device__ unsigned long long g_bucket[NEXP][NASSIGN];

// Packed fp32x2 FMA (Blackwell): d = a*b + d on two f32 lanes (dim pairs).
__device__ __forceinline__ void ffma2(unsigned long long& d,
                                      unsigned long long a,
                                      unsigned long long b) {
    asm("fma.rn.f32x2 %0, %1, %2, %0;" : "+l"(d) : "l"(a), "l"(b));
}
__device__ __forceinline__ float unpack_sum(unsigned long long v) {
    unsigned lo, hi;
    asm("mov.b64 {%0, %1}, %2;" : "=r"(lo), "=r"(hi) : "l"(v));
    return __uint_as_float(lo) + __uint_as_float(hi);
}

// One fused kernel: GEMV + softmax + top-2 + renorm + stats; LAST arriving
// block computes loss + (rare) capacity drop + resets scratch.
// 3 tokens/warp, unroll 4 -> 12 front-batched LDG.128 per body, 16 warps/SM.
__global__ __launch_bounds__(256, 2)
void router_main(const float* __restrict__ x,
                 const float* __restrict__ wg,
                 float* __restrict__ out) {
    extern __shared__ float sw[];              // 8*2048 f32 = 64 KB
    __shared__ float s_prob[NEXP];
    __shared__ int   s_cnt[NEXP];
    __shared__ int   s_base[NEXP];
    __shared__ int   s_last;

    const int tid  = threadIdx.x;
    const int warp = tid >> 5;
    const int lane = tid & 31;
    if (tid < NEXP) { s_prob[tid] = 0.0f; s_cnt[tid] = 0; }

    // stage w_gate into shared (one-time; L2-resident after first wave)
    {
        float4* sw4 = (float4*)sw;
        const float4* wg4 = (const float4*)wg;
        #pragma unroll
        for (int i = tid; i < NEXP * DIM / 4; i += 256) sw4[i] = wg4[i];
    }
    __syncthreads();

    const int tbase = blockIdx.x * TOKPB + warp * TOKPW;
    // Tail-safe row pointers: invalid tokens read row 0 (results discarded).
    const int t0 = (tbase + 0 < NTOK) ? (tbase + 0) : 0;
    const int t1 = (tbase + 1 < NTOK) ? (tbase + 1) : 0;
    const int t2 = (tbase + 2 < NTOK) ? (tbase + 2) : 0;

    const ulonglong2* xr0 = (const ulonglong2*)(x + (size_t)t0 * DIM);
    const ulonglong2* xr1 = (const ulonglong2*)(x + (size_t)t1 * DIM);
    const ulonglong2* xr2 = (const ulonglong2*)(x + (size_t)t2 * DIM);
    const ulonglong2* sw2 = (const ulonglong2*)sw;

    unsigned long long acc[TOKPW][NEXP];
    #pragma unroll
    for (int t = 0; t < TOKPW; t++)
        #pragma unroll
        for (int e = 0; e < NEXP; e++) acc[t][e] = 0ull;

    // Proven idiom (plain vector loads, dim-pair FFMA2), deeper burst:
    // unroll 4 -> 12 LDG.128 batched ahead of the FFMA2/LDS block.
    #pragma unroll 4
    for (int i = 0; i < 16; i++) {
        int c = i * 32 + lane;
        ulonglong2 x0 = xr0[c];
        ulonglong2 x1 = xr1[c];
        ulonglong2 x2 = xr2[c];
        #pragma unroll
        for (int e = 0; e < NEXP; e++) {
            ulonglong2 wv = sw2[e * (DIM / 4) + c];
            ffma2(acc[0][e], x0.x, wv.x); ffma2(acc[0][e], x0.y, wv.y);
            ffma2(acc[1][e], x1.x, wv.x); ffma2(acc[1][e], x1.y, wv.y);
            ffma2(acc[2][e], x2.x, wv.x); ffma2(acc[2][e], x2.y, wv.y);
        }
    }

    // Collapse f32x2 halves, butterfly so lanes 0..TOKPW-1 hold full logits.
    float logit[TOKPW][NEXP];
    #pragma unroll
    for (int t = 0; t < TOKPW; t++)
        #pragma unroll
        for (int e = 0; e < NEXP; e++) {
            float v = unpack_sum(acc[t][e]);
            v += __shfl_xor_sync(0xffffffffu, v, 16);
            v += __shfl_xor_sync(0xffffffffu, v, 8);
            v += __shfl_xor_sync(0xffffffffu, v, 4);
            v += __shfl_xor_sync(0xffffffffu, v, 2);
            v += __shfl_xor_sync(0xffffffffu, v, 1);
            logit[t][e] = v;
        }

    // Per-token epilogue on lanes 0..TOKPW-1 (valid tokens only).
    int i1 = 0, i2 = 0, r1 = 0, r2 = 0, n0 = 0;
    unsigned long long key1 = 0, key2 = 0;
    bool active = (lane < TOKPW) && (tbase + lane < NTOK);
    if (active) {
        int token = tbase + lane;
        float p[NEXP];
        float m = logit[lane][0];
        #pragma unroll
        for (int e = 1; e < NEXP; e++) m = fmaxf(m, logit[lane][e]);
        float s = 0.0f;
        #pragma unroll
        for (int e = 0; e < NEXP; e++) { p[e] = expf(logit[lane][e] - m); s += p[e]; }
        float inv = 1.0f / s;
        #pragma unroll
        for (int e = 0; e < NEXP; e++) p[e] *= inv;

        // top-2, ties -> lowest index
        float b1 = p[0];
        #pragma unroll
        for (int e = 1; e < NEXP; e++) if (p[e] > b1) { b1 = p[e]; i1 = e; }
        i2 = -1; float b2 = -1.0f;
        #pragma unroll
        for (int e = 0; e < NEXP; e++) if (e != i1 && p[e] > b2) { b2 = p[e]; i2 = e; }

        float ssum = b1 + b2;
        float w1 = b1 / ssum, w2 = b2 / ssum;

        n0 = token * 2;
        out[n0]     = (float)i1;
        out[n0 + 1] = (float)i2;
        out[NASSIGN + n0]     = w1;
        out[NASSIGN + n0 + 1] = w2;
        out[2 * NASSIGN + 1 + n0]     = 1.0f;
        out[2 * NASSIGN + 1 + n0 + 1] = 1.0f;

        // order-independent keys: (weight desc via bits, flat idx asc via ~n)
        key1 = ((unsigned long long)__float_as_uint(w1) << 32) |
               (unsigned)(~(unsigned)n0);
        key2 = ((unsigned long long)__float_as_uint(w2) << 32) |
               (unsigned)(~(unsigned)(n0 + 1));
        r1 = atomicAdd(&s_cnt[i1], 1);
        r2 = atomicAdd(&s_cnt[i2], 1);

        #pragma unroll
        for (int e = 0; e < NEXP; e++) atomicAdd(&s_prob[e], p[e]);
    }
    __syncthreads();

    // one global atomic per expert per block
    if (tid < NEXP) {
        s_base[tid] = s_cnt[tid] ? atomicAdd(&g_cnt[tid], s_cnt[tid]) : 0;
        atomicAdd(&g_probsum[tid], s_prob[tid]);
    }
    __syncthreads();

    if (active) {
        g_bucket[i1][s_base[i1] + r1] = key1;
        g_bucket[i2][s_base[i2] + r2] = key2;
    }
    __syncthreads();

    // ---- arrival counter: last block finalizes ----
    if (tid == 0) {
        __threadfence();
        unsigned old = atomicAdd(&g_done, 1u);
        s_last = (old == (unsigned)(gridDim.x - 1)) ? 1 : 0;
    }
    __syncthreads();
    if (!s_last) return;

    __shared__ int cnt[NEXP];
    if (tid < NEXP) cnt[tid] = __ldcg(&g_cnt[tid]);
    __syncthreads();

    if (tid == 0) {
        float imp[NEXP], imps = 0.0f;
        #pragma unroll
        for (int e = 0; e < NEXP; e++) { imp[e] = __ldcg(&g_probsum[e]); imps += imp[e]; }
        float loss = 0.0f;
        #pragma unroll
        for (int e = 0; e < NEXP; e++)
            loss += (imp[e] / imps) * ((float)cnt[e] / (float)NASSIGN);
        out[2 * NASSIGN] = (float)NEXP * loss;
    }

    // Capacity drop (rank = #{j: key > key_i}; keep iff rank < CAP). Matches
    // lexsort((-w, expert)) with flat-index tiebreak; rarely triggers
    // (expected per-expert count ~4096 << 5120).
    for (int e = 0; e < NEXP; e++) {
        int c = cnt[e];
        if (c <= CAP) continue;
        for (int i = tid; i < c; i += blockDim.x) {
            unsigned long long ki = __ldcg(&g_bucket[e][i]);
            int rank = 0;
            for (int j = 0; j < c; j++)
                rank += (__ldcg(&g_bucket[e][j]) > ki) ? 1 : 0;
            if (rank >= CAP) {
                unsigned n = ~(unsigned)(ki & 0xffffffffull);
                out[2 * NASSIGN + 1 + n] = 0.0f;
            }
        }
    }
    __syncthreads();

    if (tid < NEXP) { g_cnt[tid] = 0; g_probsum[tid] = 0.0f; }
    if (tid == 0)   { g_done = 0u; __threadfence(); }
}

extern "C" void kernel_launch(void* const* d_in, const int* in_sizes, int n_in,
                              void* d_out, int out_size) {
    const float* x  = (const float*)d_in[0];
    const float* wg = (const float*)d_in[1];
    float* out = (float*)d_out;
    (void)in_sizes; (void)n_in; (void)out_size;

    cudaFuncSetAttribute(router_main, cudaFuncAttributeMaxDynamicSharedMemorySize,
                         W_BYTES);

    router_main<<<NBLK, 256, W_BYTES>>>(x, wg, out);
}